// round 1
// baseline (speedup 1.0000x reference)
#include <cuda_runtime.h>

#define N_OUT_C 50000
#define KNN 32
#define CIN 16
#define COUT 32
#define KC 1024            // 64 taps * 16 cin
#define WT_STRIDE 1028     // padded row stride (floats) -> conflict-free float4 LDS
#define NWARP 8
#define RPW 2              // outputs per warp per pass
#define GROUP (NWARP*RPW)  // 16 outputs per CTA iteration
#define NGROUPS (N_OUT_C/GROUP)  // 3125 exactly

struct __align__(16) Smem {
    float Wt[COUT * WT_STRIDE];          // 131584 B, transposed kernel [cout][kc]
    float B[NWARP][RPW][KC];             // 65536 B
    float meta[NWARP][RPW][KNN][8];      // 16384 B  (wx0,wx1,wy0,wy1 | wz0,wz1,imp,pack)
};
// total = 213504 B

__global__ __launch_bounds__(256, 1)
void cconv_kernel(const float* __restrict__ feats,
                  const float* __restrict__ inp_points,
                  const float* __restrict__ out_points,
                  const float* __restrict__ out_extents,
                  const float* __restrict__ scale_compat,
                  const int*   __restrict__ nidx,
                  const float* __restrict__ ndist,
                  const float* __restrict__ kernW,
                  const float* __restrict__ bias,
                  float* __restrict__ out)
{
    extern __shared__ unsigned char smem_raw[];
    Smem* S = reinterpret_cast<Smem*>(smem_raw);
    const int tid  = threadIdx.x;
    const int wid  = tid >> 5;
    const int lane = tid & 31;

    // Load kernel weights, transpose [kc][cout] -> [cout][kc] (padded rows).
    for (int i = tid; i < KC * COUT; i += 256) {
        int kc = i >> 5, d = i & 31;
        S->Wt[d * WT_STRIDE + kc] = kernW[i];
    }
    const float bias_l = bias[lane];
    __syncthreads();

    for (int g = blockIdx.x; g < NGROUPS; g += gridDim.x) {
        const int obase = g * GROUP + wid * RPW;
        float den[RPW];

        __syncwarp();   // previous iteration's GEMV reads of B are done

        // ---- zero B for both output slots ----
        #pragma unroll
        for (int s = 0; s < RPW; s++) {
            float4* Bz = reinterpret_cast<float4*>(S->B[wid][s]);
            #pragma unroll
            for (int z = 0; z < (KC / 4) / 32; z++)
                Bz[z * 32 + lane] = make_float4(0.f, 0.f, 0.f, 0.f);
        }

        // ---- per-edge geometry: lane = edge, one pass per output slot ----
        #pragma unroll
        for (int s = 0; s < RPW; s++) {
            const int o   = obase + s;
            const int eid = o * KNN + lane;
            const int   nbr  = nidx[eid];
            const float dist = ndist[eid];
            const float sc   = scale_compat[eid];

            // poly6 window
            float tt  = 1.f - dist * dist;
            float win = tt * tt * tt;
            win = fminf(fmaxf(win, 0.f), 1.f);
            const float imp = sc * win;

            const float pix = inp_points[nbr * 3 + 0];
            const float piy = inp_points[nbr * 3 + 1];
            const float piz = inp_points[nbr * 3 + 2];
            const float pox = out_points[o * 3 + 0];
            const float poy = out_points[o * 3 + 1];
            const float poz = out_points[o * 3 + 2];
            const float inv = 2.f / out_extents[o];

            const float rx = (pix - pox) * inv;
            const float ry = (piy - poy) * inv;
            const float rz = (piz - poz) * inv;

            // ball_to_cube_radial
            const float r    = sqrtf(rx * rx + ry * ry + rz * rz);
            const float linf = fmaxf(fabsf(rx), fmaxf(fabsf(ry), fabsf(rz)));
            const float sfac = r / fmaxf(linf, 1e-12f);
            const float ux = rx * sfac, uy = ry * sfac, uz = rz * sfac;

            // trilinear coords in [0, 3]
            float tx = fminf(fmaxf((ux * 0.5f + 0.5f) * 3.f, 0.f), 3.f);
            float ty = fminf(fmaxf((uy * 0.5f + 0.5f) * 3.f, 0.f), 3.f);
            float tz = fminf(fmaxf((uz * 0.5f + 0.5f) * 3.f, 0.f), 3.f);
            float t0x = fminf(floorf(tx), 2.f);
            float t0y = fminf(floorf(ty), 2.f);
            float t0z = fminf(floorf(tz), 2.f);
            float fx = tx - t0x, fy = ty - t0y, fz = tz - t0z;
            int ix = (int)t0x, iy = (int)t0y, iz = (int)t0z;

            const int pack = nbr | (ix << 20) | (iy << 22) | (iz << 24);
            float4* mp = reinterpret_cast<float4*>(S->meta[wid][s][lane]);
            mp[0] = make_float4(1.f - fx, fx, 1.f - fy, fy);
            mp[1] = make_float4(1.f - fz, fz, imp, __int_as_float(pack));

            // den = sum of importances over this output's 32 edges
            float dsum = imp;
            #pragma unroll
            for (int off = 16; off; off >>= 1)
                dsum += __shfl_xor_sync(0xffffffffu, dsum, off);
            den[s] = dsum;
        }
        __syncwarp();

        // ---- accumulation: half-warp h owns output slot h, lane owns channel c ----
        {
            const int h = lane >> 4;
            const int c = lane & 15;
            float* Bp0 = S->B[wid][h];
            const float4* mbase = reinterpret_cast<const float4*>(S->meta[wid][h]);
            #pragma unroll 4
            for (int e = 0; e < KNN; e++) {
                const float4 m0 = mbase[e * 2 + 0];
                const float4 m1 = mbase[e * 2 + 1];
                const int pack = __float_as_int(m1.w);
                const int nb = pack & 0x1FFFF;
                const int ix = (pack >> 20) & 3;
                const int iy = (pack >> 22) & 3;
                const int iz = (pack >> 24) & 3;
                // base tap float offset: kf*16 + c, kf = ix*16 + iy*4 + iz
                float* Bp = Bp0 + (ix * 16 + iy * 4 + iz) * 16 + c;
                const float fe  = __ldg(&feats[nb * CIN + c]) * m1.z;  // * imp
                const float ax0 = fe * m0.x, ax1 = fe * m0.y;          // * wx
                const float v00 = ax0 * m0.z, v01 = ax0 * m0.w;        // * wy
                const float v10 = ax1 * m0.z, v11 = ax1 * m0.w;
                // dx: +256 floats, dy: +64, dz: +16
                Bp[0]   += v00 * m1.x;
                Bp[16]  += v00 * m1.y;
                Bp[64]  += v01 * m1.x;
                Bp[80]  += v01 * m1.y;
                Bp[256] += v10 * m1.x;
                Bp[272] += v10 * m1.y;
                Bp[320] += v11 * m1.x;
                Bp[336] += v11 * m1.y;
            }
        }
        __syncwarp();

        // ---- GEMV: lane = cout, 2 outputs share every W load ----
        {
            const float4* wrow = reinterpret_cast<const float4*>(S->Wt + lane * WT_STRIDE);
            const float4* B0 = reinterpret_cast<const float4*>(S->B[wid][0]);
            const float4* B1 = reinterpret_cast<const float4*>(S->B[wid][1]);
            float a0 = 0.f, a1 = 0.f;
            #pragma unroll 8
            for (int q = 0; q < KC / 4; q++) {
                const float4 w  = wrow[q];
                const float4 b0 = B0[q];
                const float4 b1 = B1[q];
                a0 = fmaf(w.x, b0.x, a0); a0 = fmaf(w.y, b0.y, a0);
                a0 = fmaf(w.z, b0.z, a0); a0 = fmaf(w.w, b0.w, a0);
                a1 = fmaf(w.x, b1.x, a1); a1 = fmaf(w.y, b1.y, a1);
                a1 = fmaf(w.z, b1.z, a1); a1 = fmaf(w.w, b1.w, a1);
            }
            const float d0 = den[0] > 0.f ? den[0] : 1.f;
            const float d1 = den[1] > 0.f ? den[1] : 1.f;
            out[(obase + 0) * COUT + lane] = fmaxf(a0 / d0 + bias_l, 0.f);
            out[(obase + 1) * COUT + lane] = fmaxf(a1 / d1 + bias_l, 0.f);
        }
    }
}

extern "C" void kernel_launch(void* const* d_in, const int* in_sizes, int n_in,
                              void* d_out, int out_size)
{
    const float* feats        = (const float*)d_in[0];
    const float* inp_points   = (const float*)d_in[1];
    const float* out_points   = (const float*)d_in[2];
    const float* out_extents  = (const float*)d_in[3];
    const float* scale_compat = (const float*)d_in[4];
    const int*   nidx         = (const int*)  d_in[5];
    // d_in[6] = neighbors_row_splits: fixed-degree (arange * K), not needed
    const float* ndist        = (const float*)d_in[7];
    const float* kernW        = (const float*)d_in[8];
    const float* bias         = (const float*)d_in[9];
    float* out = (float*)d_out;

    cudaFuncSetAttribute(cconv_kernel,
                         cudaFuncAttributeMaxDynamicSharedMemorySize,
                         (int)sizeof(Smem));
    cconv_kernel<<<148, 256, sizeof(Smem)>>>(feats, inp_points, out_points,
                                             out_extents, scale_compat, nidx,
                                             ndist, kernW, bias, out);
}

// round 3
// speedup vs baseline: 1.1580x; 1.1580x over previous
#include <cuda_runtime.h>

#define N_OUT_C 50000
#define KNN 32
#define CIN 16
#define COUT 32
#define KC 1024            // 64 taps * 16 cin
#define WT_STRIDE 1028     // padded row stride (floats) -> conflict-free float4 LDS
#define NWARP 8
#define GROUP 16           // outputs per CTA iteration (2 per warp, pair-interleaved)
#define NGROUPS (N_OUT_C/GROUP)  // 3125 exactly

struct __align__(16) Smem {
    float Wt[COUT * WT_STRIDE];      // 131584 B, transposed kernel [cout][kc]
    float B[NWARP][KC * 2];          // 65536 B: pair-interleaved [pair][kc][2]
    float4 meta4[NWARP][2][KNN];     // 8192 B: (fx, fy, fz, imp)
    int   packs[NWARP][2][KNN];      // 2048 B: nbr | ix<<20 | iy<<22 | iz<<24
    float part[NWARP][NWARP][COUT][2]; // 16384 B: per-warp GEMM partials
    float dens[2][GROUP];            // 128 B, double-buffered by iteration parity
};
// total = 223872 B

__device__ __forceinline__ void fma2(unsigned long long& acc,
                                     unsigned long long a,
                                     unsigned long long b) {
    asm("fma.rn.f32x2 %0, %1, %2, %0;" : "+l"(acc) : "l"(a), "l"(b));
}
__device__ __forceinline__ unsigned long long dup2(float x) {
    unsigned long long r; unsigned xi = __float_as_uint(x);
    asm("mov.b64 %0, {%1, %1};" : "=l"(r) : "r"(xi));
    return r;
}

__global__ __launch_bounds__(256, 1)
void cconv_kernel(const float* __restrict__ feats,
                  const float* __restrict__ inp_points,
                  const float* __restrict__ out_points,
                  const float* __restrict__ out_extents,
                  const float* __restrict__ scale_compat,
                  const int*   __restrict__ nidx,
                  const float* __restrict__ ndist,
                  const float* __restrict__ kernW,
                  const float* __restrict__ bias,
                  float* __restrict__ out)
{
    extern __shared__ unsigned char smem_raw[];
    Smem* S = reinterpret_cast<Smem*>(smem_raw);
    const int tid  = threadIdx.x;
    const int wid  = tid >> 5;
    const int lane = tid & 31;

    // Load kernel weights, transpose [kc][cout] -> [cout][kc] (padded rows).
    for (int i = tid; i < KC * COUT; i += 256) {
        int kc = i >> 5, d = i & 31;
        S->Wt[d * WT_STRIDE + kc] = kernW[i];
    }
    const float bias_l = bias[tid & 31];
    __syncthreads();

    int par = 0;
    for (int g = blockIdx.x; g < NGROUPS; g += gridDim.x, par ^= 1) {
        const int obase = g * GROUP + wid * 2;

        // ================= Phase A: zero B, geometry, scatter =================
        // ---- zero this warp's pair-interleaved B ----
        {
            float4* Bz = reinterpret_cast<float4*>(S->B[wid]);
            #pragma unroll
            for (int z = 0; z < (KC * 2 / 4) / 32; z++)
                Bz[z * 32 + lane] = make_float4(0.f, 0.f, 0.f, 0.f);
        }

        // ---- per-edge geometry: lane = edge, one pass per output slot ----
        #pragma unroll
        for (int s = 0; s < 2; s++) {
            const int o   = obase + s;
            const int eid = o * KNN + lane;
            const int   nbr  = nidx[eid];
            const float dist = ndist[eid];
            const float sc   = scale_compat[eid];

            float tt  = 1.f - dist * dist;
            float win = tt * tt * tt;
            win = fminf(fmaxf(win, 0.f), 1.f);
            const float imp = sc * win;

            const float pix = inp_points[nbr * 3 + 0];
            const float piy = inp_points[nbr * 3 + 1];
            const float piz = inp_points[nbr * 3 + 2];
            const float pox = out_points[o * 3 + 0];
            const float poy = out_points[o * 3 + 1];
            const float poz = out_points[o * 3 + 2];
            const float inv = 2.f / out_extents[o];

            const float rx = (pix - pox) * inv;
            const float ry = (piy - poy) * inv;
            const float rz = (piz - poz) * inv;

            const float r    = sqrtf(rx * rx + ry * ry + rz * rz);
            const float linf = fmaxf(fabsf(rx), fmaxf(fabsf(ry), fabsf(rz)));
            const float sfac = r / fmaxf(linf, 1e-12f);
            const float ux = rx * sfac, uy = ry * sfac, uz = rz * sfac;

            float tx = fminf(fmaxf((ux * 0.5f + 0.5f) * 3.f, 0.f), 3.f);
            float ty = fminf(fmaxf((uy * 0.5f + 0.5f) * 3.f, 0.f), 3.f);
            float tz = fminf(fmaxf((uz * 0.5f + 0.5f) * 3.f, 0.f), 3.f);
            float t0x = fminf(floorf(tx), 2.f);
            float t0y = fminf(floorf(ty), 2.f);
            float t0z = fminf(floorf(tz), 2.f);
            float fx = tx - t0x, fy = ty - t0y, fz = tz - t0z;
            int ix = (int)t0x, iy = (int)t0y, iz = (int)t0z;

            S->meta4[wid][s][lane] = make_float4(fx, fy, fz, imp);
            S->packs[wid][s][lane] = nbr | (ix << 20) | (iy << 22) | (iz << 24);

            float dsum = imp;
            #pragma unroll
            for (int off = 16; off; off >>= 1)
                dsum += __shfl_xor_sync(0xffffffffu, dsum, off);
            if (lane == 0) S->dens[par][wid * 2 + s] = dsum;
        }
        __syncwarp();

        // ---- scatter: half-warp h -> slot h; bank = (2c+h)%32, conflict-free ----
        {
            const int h = lane >> 4;
            const int c = lane & 15;
            float* Bw = S->B[wid];
            const float4* m4 = S->meta4[wid][h];
            const int*    pk = S->packs[wid][h];
            #pragma unroll 4
            for (int e = 0; e < KNN; e++) {
                const float4 m = m4[e];
                const int p  = pk[e];
                const int nb = p & 0xFFFFF;
                const int ix = (p >> 20) & 3;
                const int iy = (p >> 22) & 3;
                const int iz = (p >> 24) & 3;
                const float fe  = __ldg(&feats[nb * CIN + c]) * m.w;
                const float ax1 = fe * m.x,  ax0 = fe  - ax1;
                const float v01 = ax0 * m.y, v00 = ax0 - v01;
                const float v11 = ax1 * m.y, v10 = ax1 - v11;
                const float wz1 = m.z, wz0 = 1.f - m.z;
                // tap stride = 32 floats (16 ch * 2 outputs); dz:+32 dy:+128 dx:+512
                float* Bp = Bw + ((ix * 16 + iy * 4 + iz) * 32 + c * 2 + h);
                Bp[0]   += v00 * wz0;  Bp[32]  += v00 * wz1;
                Bp[128] += v01 * wz0;  Bp[160] += v01 * wz1;
                Bp[512] += v10 * wz0;  Bp[544] += v10 * wz1;
                Bp[640] += v11 * wz0;  Bp[672] += v11 * wz1;
            }
        }
        __syncthreads();

        // ========== Phase B: cooperative GEMM, warp owns kc-slice of W ==========
        {
            // lane = cout; this warp's 128-kc slice of W (read ONCE per group)
            const float4* wrow = reinterpret_cast<const float4*>(
                                     S->Wt + lane * WT_STRIDE) + wid * 32;
            const int kofs_base = wid * 128 * 2;   // float offset into B[p]
            unsigned long long acc[NWARP];
            #pragma unroll
            for (int p = 0; p < NWARP; p++) acc[p] = 0ull;  // (0.f, 0.f)

            #pragma unroll 4
            for (int q = 0; q < 32; q++) {
                const float4 w4 = wrow[q];
                const unsigned long long w2a = dup2(w4.x);
                const unsigned long long w2b = dup2(w4.y);
                const unsigned long long w2c = dup2(w4.z);
                const unsigned long long w2d = dup2(w4.w);
                const int kofs = kofs_base + q * 8;   // 4 kc * 2
                #pragma unroll
                for (int p = 0; p < NWARP; p++) {
                    const ulonglong2* bp =
                        reinterpret_cast<const ulonglong2*>(S->B[p] + kofs);
                    const ulonglong2 b01 = bp[0];   // kc+0, kc+1 (x2 outputs)
                    const ulonglong2 b23 = bp[1];   // kc+2, kc+3
                    fma2(acc[p], w2a, b01.x);
                    fma2(acc[p], w2b, b01.y);
                    fma2(acc[p], w2c, b23.x);
                    fma2(acc[p], w2d, b23.y);
                }
            }
            // store partials
            #pragma unroll
            for (int p = 0; p < NWARP; p++) {
                unsigned lo, hi;
                asm("mov.b64 {%0, %1}, %2;" : "=r"(lo), "=r"(hi) : "l"(acc[p]));
                float2 st = make_float2(__uint_as_float(lo), __uint_as_float(hi));
                *reinterpret_cast<float2*>(&S->part[wid][p][lane][0]) = st;
            }
        }
        __syncthreads();

        // ============ Phase C: reduce partials, normalize, epilogue ============
        #pragma unroll
        for (int r = tid; r < GROUP * COUT; r += 256) {
            const int o = r >> 5, c = r & 31;
            const int p = o >> 1, h = o & 1;
            float ssum = 0.f;
            #pragma unroll
            for (int w = 0; w < NWARP; w++) ssum += S->part[w][p][c][h];
            float dn = S->dens[par][o];
            dn = dn > 0.f ? dn : 1.f;
            out[(g * GROUP + o) * COUT + c] = fmaxf(ssum / dn + bias_l, 0.f);
        }
    }
}

extern "C" void kernel_launch(void* const* d_in, const int* in_sizes, int n_in,
                              void* d_out, int out_size)
{
    const float* feats        = (const float*)d_in[0];
    const float* inp_points   = (const float*)d_in[1];
    const float* out_points   = (const float*)d_in[2];
    const float* out_extents  = (const float*)d_in[3];
    const float* scale_compat = (const float*)d_in[4];
    const int*   nidx         = (const int*)  d_in[5];
    // d_in[6] = neighbors_row_splits: fixed-degree (arange * K), not needed
    const float* ndist        = (const float*)d_in[7];
    const float* kernW        = (const float*)d_in[8];
    const float* bias         = (const float*)d_in[9];
    float* out = (float*)d_out;

    cudaFuncSetAttribute(cconv_kernel,
                         cudaFuncAttributeMaxDynamicSharedMemorySize,
                         (int)sizeof(Smem));
    cconv_kernel<<<148, 256, sizeof(Smem)>>>(feats, inp_points, out_points,
                                             out_extents, scale_compat, nidx,
                                             ndist, kernW, bias, out);
}

// round 4
// speedup vs baseline: 1.5997x; 1.3814x over previous
#include <cuda_runtime.h>

#define N_OUT_C 50000
#define KNN 32
#define CIN 16
#define COUT 32
#define KC 1024            // 64 taps * 16 cin
#define NWARP 8
#define GROUP 16           // outputs per CTA iteration (2 per warp, pair-interleaved)
#define NGROUPS (N_OUT_C/GROUP)  // 3125 exactly

struct __align__(16) Smem {
    float B[NWARP][KC * 2];            // 65536 B: pair-interleaved [pair][kc][2]
    float4 meta4[NWARP][2][KNN];       // 8192 B: (fx, fy, fz, imp)
    int   packs[NWARP][2][KNN];        // 2048 B: nbr | ix<<20 | iy<<22 | iz<<24
    float part[NWARP][NWARP][COUT][2]; // 16384 B: per-warp GEMM partials
    float dens[2][GROUP];              // 128 B, double-buffered by iteration parity
};
// total = 92288 B -> 2 CTAs per SM

__device__ __forceinline__ void fma2(unsigned long long& acc,
                                     unsigned long long a,
                                     unsigned long long b) {
    asm("fma.rn.f32x2 %0, %1, %2, %0;" : "+l"(acc) : "l"(a), "l"(b));
}
__device__ __forceinline__ unsigned long long dup2(float x) {
    unsigned long long r; unsigned xi = __float_as_uint(x);
    asm("mov.b64 %0, {%1, %1};" : "=l"(r) : "r"(xi));
    return r;
}

__global__ __launch_bounds__(256, 2)
void cconv_kernel(const float* __restrict__ feats,
                  const float* __restrict__ inp_points,
                  const float* __restrict__ out_points,
                  const float* __restrict__ out_extents,
                  const float* __restrict__ scale_compat,
                  const int*   __restrict__ nidx,
                  const float* __restrict__ ndist,
                  const float* __restrict__ kernW,
                  const float* __restrict__ bias,
                  float* __restrict__ out)
{
    extern __shared__ unsigned char smem_raw[];
    Smem* S = reinterpret_cast<Smem*>(smem_raw);
    const int tid  = threadIdx.x;
    const int wid  = tid >> 5;
    const int lane = tid & 31;

    const float bias_l = bias[lane];
    // per-warp W base: lane = cout, row stride COUT floats, coalesced LDG
    const float* wbase = kernW + (size_t)(wid * 128) * COUT + lane;

    int par = 0;
    for (int g = blockIdx.x; g < NGROUPS; g += gridDim.x, par ^= 1) {
        const int obase = g * GROUP + wid * 2;

        // ================= Phase A: zero B, geometry, scatter =================
        {
            float4* Bz = reinterpret_cast<float4*>(S->B[wid]);
            #pragma unroll
            for (int z = 0; z < (KC * 2 / 4) / 32; z++)
                Bz[z * 32 + lane] = make_float4(0.f, 0.f, 0.f, 0.f);
        }

        // ---- per-edge geometry: lane = edge, one pass per output slot ----
        #pragma unroll
        for (int s = 0; s < 2; s++) {
            const int o   = obase + s;
            const int eid = o * KNN + lane;
            const int   nbr  = nidx[eid];
            const float dist = ndist[eid];
            const float sc   = scale_compat[eid];

            float tt  = 1.f - dist * dist;
            float win = tt * tt * tt;
            win = fminf(fmaxf(win, 0.f), 1.f);
            const float imp = sc * win;

            const float pix = inp_points[nbr * 3 + 0];
            const float piy = inp_points[nbr * 3 + 1];
            const float piz = inp_points[nbr * 3 + 2];
            const float pox = out_points[o * 3 + 0];
            const float poy = out_points[o * 3 + 1];
            const float poz = out_points[o * 3 + 2];
            const float inv = __fdividef(2.f, out_extents[o]);

            const float rx = (pix - pox) * inv;
            const float ry = (piy - poy) * inv;
            const float rz = (piz - poz) * inv;

            const float r    = sqrtf(rx * rx + ry * ry + rz * rz);
            const float linf = fmaxf(fabsf(rx), fmaxf(fabsf(ry), fabsf(rz)));
            const float sfac = __fdividef(r, fmaxf(linf, 1e-12f));
            const float ux = rx * sfac, uy = ry * sfac, uz = rz * sfac;

            float tx = fminf(fmaxf((ux * 0.5f + 0.5f) * 3.f, 0.f), 3.f);
            float ty = fminf(fmaxf((uy * 0.5f + 0.5f) * 3.f, 0.f), 3.f);
            float tz = fminf(fmaxf((uz * 0.5f + 0.5f) * 3.f, 0.f), 3.f);
            float t0x = fminf(floorf(tx), 2.f);
            float t0y = fminf(floorf(ty), 2.f);
            float t0z = fminf(floorf(tz), 2.f);
            float fx = tx - t0x, fy = ty - t0y, fz = tz - t0z;
            int ix = (int)t0x, iy = (int)t0y, iz = (int)t0z;

            S->meta4[wid][s][lane] = make_float4(fx, fy, fz, imp);
            S->packs[wid][s][lane] = nbr | (ix << 20) | (iy << 22) | (iz << 24);

            float dsum = imp;
            #pragma unroll
            for (int off = 16; off; off >>= 1)
                dsum += __shfl_xor_sync(0xffffffffu, dsum, off);
            if (lane == 0) S->dens[par][wid * 2 + s] = dsum;
        }
        __syncwarp();

        // ---- scatter: half-warp h -> slot h; bank = (2c+h)%32, conflict-free ----
        {
            const int h = lane >> 4;
            const int c = lane & 15;
            float* Bw = S->B[wid];
            const float4* m4 = S->meta4[wid][h];
            const int*    pk = S->packs[wid][h];
            #pragma unroll 4
            for (int e = 0; e < KNN; e++) {
                const float4 m = m4[e];
                const int p  = pk[e];
                const int nb = p & 0xFFFFF;
                const int ix = (p >> 20) & 3;
                const int iy = (p >> 22) & 3;
                const int iz = (p >> 24) & 3;
                const float fe  = __ldg(&feats[nb * CIN + c]) * m.w;
                const float ax1 = fe * m.x,  ax0 = fe  - ax1;
                const float v01 = ax0 * m.y, v00 = ax0 - v01;
                const float v11 = ax1 * m.y, v10 = ax1 - v11;
                const float wz1 = m.z, wz0 = 1.f - m.z;
                // tap stride = 32 floats (16 ch * 2 outputs); dz:+32 dy:+128 dx:+512
                float* Bp = Bw + ((ix * 16 + iy * 4 + iz) * 32 + c * 2 + h);
                Bp[0]   += v00 * wz0;  Bp[32]  += v00 * wz1;
                Bp[128] += v01 * wz0;  Bp[160] += v01 * wz1;
                Bp[512] += v10 * wz0;  Bp[544] += v10 * wz1;
                Bp[640] += v11 * wz0;  Bp[672] += v11 * wz1;
            }
        }
        __syncthreads();

        // ========== Phase B: cooperative GEMM, warp owns 128-kc slice ==========
        // W read straight from gmem (L2-hot): lane = cout, coalesced 128B rows.
        {
            const int kofs_base = wid * 128 * 2;   // float offset into B[p]
            unsigned long long acc[NWARP];
            #pragma unroll
            for (int p = 0; p < NWARP; p++) acc[p] = 0ull;  // (0.f, 0.f)

            #pragma unroll 4
            for (int q = 0; q < 32; q++) {
                const float* wq = wbase + q * 4 * COUT;
                const unsigned long long w2a = dup2(__ldg(wq));
                const unsigned long long w2b = dup2(__ldg(wq + COUT));
                const unsigned long long w2c = dup2(__ldg(wq + 2 * COUT));
                const unsigned long long w2d = dup2(__ldg(wq + 3 * COUT));
                const int kofs = kofs_base + q * 8;   // 4 kc * 2
                #pragma unroll
                for (int p = 0; p < NWARP; p++) {
                    const ulonglong2* bp =
                        reinterpret_cast<const ulonglong2*>(S->B[p] + kofs);
                    const ulonglong2 b01 = bp[0];   // kc+0, kc+1 (x2 outputs)
                    const ulonglong2 b23 = bp[1];   // kc+2, kc+3
                    fma2(acc[p], w2a, b01.x);
                    fma2(acc[p], w2b, b01.y);
                    fma2(acc[p], w2c, b23.x);
                    fma2(acc[p], w2d, b23.y);
                }
            }
            // store partials
            #pragma unroll
            for (int p = 0; p < NWARP; p++) {
                unsigned lo, hi;
                asm("mov.b64 {%0, %1}, %2;" : "=r"(lo), "=r"(hi) : "l"(acc[p]));
                float2 st = make_float2(__uint_as_float(lo), __uint_as_float(hi));
                *reinterpret_cast<float2*>(&S->part[wid][p][lane][0]) = st;
            }
        }
        __syncthreads();

        // ============ Phase C: reduce partials, normalize, epilogue ============
        #pragma unroll
        for (int r = tid; r < GROUP * COUT; r += 256) {
            const int o = r >> 5, c = r & 31;
            const int p = o >> 1, h = o & 1;
            float ssum = 0.f;
            #pragma unroll
            for (int w = 0; w < NWARP; w++) ssum += S->part[w][p][c][h];
            float dn = S->dens[par][o];
            dn = dn > 0.f ? dn : 1.f;
            out[(g * GROUP + o) * COUT + c] = fmaxf(ssum / dn + bias_l, 0.f);
        }
    }
}

extern "C" void kernel_launch(void* const* d_in, const int* in_sizes, int n_in,
                              void* d_out, int out_size)
{
    const float* feats        = (const float*)d_in[0];
    const float* inp_points   = (const float*)d_in[1];
    const float* out_points   = (const float*)d_in[2];
    const float* out_extents  = (const float*)d_in[3];
    const float* scale_compat = (const float*)d_in[4];
    const int*   nidx         = (const int*)  d_in[5];
    // d_in[6] = neighbors_row_splits: fixed-degree (arange * K), not needed
    const float* ndist        = (const float*)d_in[7];
    const float* kernW        = (const float*)d_in[8];
    const float* bias         = (const float*)d_in[9];
    float* out = (float*)d_out;

    cudaFuncSetAttribute(cconv_kernel,
                         cudaFuncAttributeMaxDynamicSharedMemorySize,
                         (int)sizeof(Smem));
    cconv_kernel<<<296, 256, sizeof(Smem)>>>(feats, inp_points, out_points,
                                             out_extents, scale_compat, nidx,
                                             ndist, kernW, bias, out);
}

// round 5
// speedup vs baseline: 1.6009x; 1.0007x over previous
#include <cuda_runtime.h>

#define N_OUT_C 50000
#define KNN 32
#define CIN 16
#define COUT 32
#define KC 1024            // 64 taps * 16 cin
#define NWARP 8
#define GROUP 16           // outputs per CTA iteration (2 per warp, pair-interleaved)
#define NGROUPS (N_OUT_C/GROUP)  // 3125 exactly

struct __align__(16) Smem {
    float B[NWARP][KC * 2];            // 65536 B: pair-interleaved [pair][kc][2]
    float4 meta4[NWARP][2][KNN];       // 8192 B: (fx, fy, fz, imp)
    int   packs[NWARP][2][KNN];        // 2048 B: nbr | ix<<20 | iy<<22 | iz<<24
    float part[NWARP][NWARP][COUT][2]; // 16384 B: per-warp GEMM partials
    float dens[2][GROUP];              // 128 B, double-buffered by iteration parity
};
// total = 92288 B -> 2 CTAs per SM

__device__ __forceinline__ void fma2(unsigned long long& acc,
                                     unsigned long long a,
                                     unsigned long long b) {
    asm("fma.rn.f32x2 %0, %1, %2, %0;" : "+l"(acc) : "l"(a), "l"(b));
}
__device__ __forceinline__ unsigned long long dup2(float x) {
    unsigned long long r; unsigned xi = __float_as_uint(x);
    asm("mov.b64 %0, {%1, %1};" : "=l"(r) : "r"(xi));
    return r;
}

__global__ __launch_bounds__(256, 2)
void cconv_kernel(const float* __restrict__ feats,
                  const float* __restrict__ inp_points,
                  const float* __restrict__ out_points,
                  const float* __restrict__ out_extents,
                  const float* __restrict__ scale_compat,
                  const int*   __restrict__ nidx,
                  const float* __restrict__ ndist,
                  const float* __restrict__ kernW,
                  const float* __restrict__ bias,
                  float* __restrict__ out)
{
    extern __shared__ unsigned char smem_raw[];
    Smem* S = reinterpret_cast<Smem*>(smem_raw);
    const int tid  = threadIdx.x;
    const int wid  = tid >> 5;
    const int lane = tid & 31;

    const float bias_l = bias[lane];
    // per-warp W base: lane = cout, row stride COUT floats, coalesced LDG
    const float* wbase = kernW + (size_t)(wid * 128) * COUT + lane;

    int par = 0;
    for (int g = blockIdx.x; g < NGROUPS; g += gridDim.x, par ^= 1) {
        const int obase = g * GROUP + wid * 2;

        // ================= Phase A: zero B, geometry, scatter =================
        {
            float4* Bz = reinterpret_cast<float4*>(S->B[wid]);
            #pragma unroll
            for (int z = 0; z < (KC * 2 / 4) / 32; z++)
                Bz[z * 32 + lane] = make_float4(0.f, 0.f, 0.f, 0.f);
        }

        // ---- per-edge geometry: lane = edge, one pass per output slot ----
        #pragma unroll
        for (int s = 0; s < 2; s++) {
            const int o   = obase + s;
            const int eid = o * KNN + lane;
            const int   nbr  = nidx[eid];
            const float dist = ndist[eid];
            const float sc   = scale_compat[eid];

            float tt  = 1.f - dist * dist;
            float win = tt * tt * tt;
            win = fminf(fmaxf(win, 0.f), 1.f);
            const float imp = sc * win;

            const float pix = inp_points[nbr * 3 + 0];
            const float piy = inp_points[nbr * 3 + 1];
            const float piz = inp_points[nbr * 3 + 2];
            const float pox = out_points[o * 3 + 0];
            const float poy = out_points[o * 3 + 1];
            const float poz = out_points[o * 3 + 2];
            const float inv = __fdividef(2.f, out_extents[o]);

            const float rx = (pix - pox) * inv;
            const float ry = (piy - poy) * inv;
            const float rz = (piz - poz) * inv;

            const float r    = sqrtf(rx * rx + ry * ry + rz * rz);
            const float linf = fmaxf(fabsf(rx), fmaxf(fabsf(ry), fabsf(rz)));
            const float sfac = __fdividef(r, fmaxf(linf, 1e-12f));
            const float ux = rx * sfac, uy = ry * sfac, uz = rz * sfac;

            float tx = fminf(fmaxf((ux * 0.5f + 0.5f) * 3.f, 0.f), 3.f);
            float ty = fminf(fmaxf((uy * 0.5f + 0.5f) * 3.f, 0.f), 3.f);
            float tz = fminf(fmaxf((uz * 0.5f + 0.5f) * 3.f, 0.f), 3.f);
            float t0x = fminf(floorf(tx), 2.f);
            float t0y = fminf(floorf(ty), 2.f);
            float t0z = fminf(floorf(tz), 2.f);
            float fx = tx - t0x, fy = ty - t0y, fz = tz - t0z;
            int ix = (int)t0x, iy = (int)t0y, iz = (int)t0z;

            S->meta4[wid][s][lane] = make_float4(fx, fy, fz, imp);
            S->packs[wid][s][lane] = nbr | (ix << 20) | (iy << 22) | (iz << 24);

            float dsum = imp;
            #pragma unroll
            for (int off = 16; off; off >>= 1)
                dsum += __shfl_xor_sync(0xffffffffu, dsum, off);
            if (lane == 0) S->dens[par][wid * 2 + s] = dsum;
        }
        __syncwarp();

        // ---- scatter: half-warp h -> slot h; bank = (2c+h)%32, conflict-free ----
        {
            const int h = lane >> 4;
            const int c = lane & 15;
            float* Bw = S->B[wid];
            const float4* m4 = S->meta4[wid][h];
            const int*    pk = S->packs[wid][h];
            #pragma unroll 4
            for (int e = 0; e < KNN; e++) {
                const float4 m = m4[e];
                const int p  = pk[e];
                const int nb = p & 0xFFFFF;
                const int ix = (p >> 20) & 3;
                const int iy = (p >> 22) & 3;
                const int iz = (p >> 24) & 3;
                const float fe  = __ldg(&feats[nb * CIN + c]) * m.w;
                const float ax1 = fe * m.x,  ax0 = fe  - ax1;
                const float v01 = ax0 * m.y, v00 = ax0 - v01;
                const float v11 = ax1 * m.y, v10 = ax1 - v11;
                const float wz1 = m.z, wz0 = 1.f - m.z;
                // tap stride = 32 floats (16 ch * 2 outputs); dz:+32 dy:+128 dx:+512
                float* Bp = Bw + ((ix * 16 + iy * 4 + iz) * 32 + c * 2 + h);
                Bp[0]   += v00 * wz0;  Bp[32]  += v00 * wz1;
                Bp[128] += v01 * wz0;  Bp[160] += v01 * wz1;
                Bp[512] += v10 * wz0;  Bp[544] += v10 * wz1;
                Bp[640] += v11 * wz0;  Bp[672] += v11 * wz1;
            }
        }
        __syncthreads();

        // ========== Phase B: cooperative GEMM, warp owns 128-kc slice ==========
        // W read straight from gmem (L2-hot): lane = cout, coalesced 128B rows.
        {
            const int kofs_base = wid * 128 * 2;   // float offset into B[p]
            unsigned long long acc[NWARP];
            #pragma unroll
            for (int p = 0; p < NWARP; p++) acc[p] = 0ull;  // (0.f, 0.f)

            #pragma unroll 4
            for (int q = 0; q < 32; q++) {
                const float* wq = wbase + q * 4 * COUT;
                const unsigned long long w2a = dup2(__ldg(wq));
                const unsigned long long w2b = dup2(__ldg(wq + COUT));
                const unsigned long long w2c = dup2(__ldg(wq + 2 * COUT));
                const unsigned long long w2d = dup2(__ldg(wq + 3 * COUT));
                const int kofs = kofs_base + q * 8;   // 4 kc * 2
                #pragma unroll
                for (int p = 0; p < NWARP; p++) {
                    const ulonglong2* bp =
                        reinterpret_cast<const ulonglong2*>(S->B[p] + kofs);
                    const ulonglong2 b01 = bp[0];   // kc+0, kc+1 (x2 outputs)
                    const ulonglong2 b23 = bp[1];   // kc+2, kc+3
                    fma2(acc[p], w2a, b01.x);
                    fma2(acc[p], w2b, b01.y);
                    fma2(acc[p], w2c, b23.x);
                    fma2(acc[p], w2d, b23.y);
                }
            }
            // store partials
            #pragma unroll
            for (int p = 0; p < NWARP; p++) {
                unsigned lo, hi;
                asm("mov.b64 {%0, %1}, %2;" : "=r"(lo), "=r"(hi) : "l"(acc[p]));
                float2 st = make_float2(__uint_as_float(lo), __uint_as_float(hi));
                *reinterpret_cast<float2*>(&S->part[wid][p][lane][0]) = st;
            }
        }
        __syncthreads();

        // ============ Phase C: reduce partials, normalize, epilogue ============
        #pragma unroll
        for (int r = tid; r < GROUP * COUT; r += 256) {
            const int o = r >> 5, c = r & 31;
            const int p = o >> 1, h = o & 1;
            float ssum = 0.f;
            #pragma unroll
            for (int w = 0; w < NWARP; w++) ssum += S->part[w][p][c][h];
            float dn = S->dens[par][o];
            dn = dn > 0.f ? dn : 1.f;
            out[(g * GROUP + o) * COUT + c] = fmaxf(ssum / dn + bias_l, 0.f);
        }
    }
}

extern "C" void kernel_launch(void* const* d_in, const int* in_sizes, int n_in,
                              void* d_out, int out_size)
{
    const float* feats        = (const float*)d_in[0];
    const float* inp_points   = (const float*)d_in[1];
    const float* out_points   = (const float*)d_in[2];
    const float* out_extents  = (const float*)d_in[3];
    const float* scale_compat = (const float*)d_in[4];
    const int*   nidx         = (const int*)  d_in[5];
    // d_in[6] = neighbors_row_splits: fixed-degree (arange * K), not needed
    const float* ndist        = (const float*)d_in[7];
    const float* kernW        = (const float*)d_in[8];
    const float* bias         = (const float*)d_in[9];
    float* out = (float*)d_out;

    cudaFuncSetAttribute(cconv_kernel,
                         cudaFuncAttributeMaxDynamicSharedMemorySize,
                         (int)sizeof(Smem));
    cconv_kernel<<<296, 256, sizeof(Smem)>>>(feats, inp_points, out_points,
                                             out_extents, scale_compat, nidx,
                                             ndist, kernW, bias, out);
}

// round 8
// speedup vs baseline: 2.0678x; 1.2917x over previous
#include <cuda_runtime.h>
#include <cuda_fp16.h>
#include <cstdint>

#define N_OUT_C 50000
#define KNN 32
#define CIN 16
#define COUT 32
#define KC 1024
#define MTILE 256
#define NTILES 196              // 196*256 = 50176 >= 50000
#define WSTRIDE 1032            // padded halfs per cout row (conflict-free LDS)

// ============== device scratch (static, zero-init, no allocations) ==========
__device__ __half g_B16[(size_t)50176 * KC];      // 102.8 MB row-major fp16
__device__ __half g_WTh[COUT * WSTRIDE];          // W hi plane, [cout][kc] padded
__device__ __half g_WTl[COUT * WSTRIDE];          // W lo plane
__device__ float  g_den[N_OUT_C];

__device__ __forceinline__ uint32_t smem_u32(const void* p) {
    uint32_t a;
    asm("{ .reg .u64 t; cvta.to.shared.u64 t, %1; cvt.u32.u64 %0, t; }"
        : "=r"(a) : "l"(p));
    return a;
}

// ===================== K0: W -> fp16 hi/lo transposed ======================
__global__ void k0_prep(const float* __restrict__ kernW) {
    int i = blockIdx.x * 256 + threadIdx.x;
    if (i >= KC * COUT) return;
    int kc = i >> 5, d = i & 31;
    float w = kernW[i];
    __half hi = __float2half_rn(w);
    __half lo = __float2half_rn(w - __half2float(hi));
    g_WTh[d * WSTRIDE + kc] = hi;
    g_WTl[d * WSTRIDE + kc] = lo;
}

// ============== K1: geometry + conflict-free scatter + fp16 writeout ========
#define NW1 4
#define GROUP1 8
#define NGROUPS1 (N_OUT_C / GROUP1)   // 6250

struct __align__(16) Smem1 {
    float  B[NW1][KC * 2];        // 32768 B, pair-interleaved [kc][2 outs]
    float4 meta4[NW1][2][KNN];    // 4096 B
    int    packs[NW1][2][KNN];    // 1024 B
};                                // 37888 B -> 6 CTAs/SM

__global__ __launch_bounds__(128, 6)
void k1_scatter(const float* __restrict__ feats,
                const float* __restrict__ inp_points,
                const float* __restrict__ out_points,
                const float* __restrict__ out_extents,
                const float* __restrict__ scale_compat,
                const int*   __restrict__ nidx,
                const float* __restrict__ ndist)
{
    extern __shared__ unsigned char raw1[];
    Smem1* S = reinterpret_cast<Smem1*>(raw1);
    const int tid = threadIdx.x, wid = tid >> 5, lane = tid & 31;

    for (int g = blockIdx.x; g < NGROUPS1; g += gridDim.x) {
        const int obase = g * GROUP1 + wid * 2;

        {   // zero B
            float4* Bz = reinterpret_cast<float4*>(S->B[wid]);
            #pragma unroll
            for (int z = 0; z < 16; z++)
                Bz[z * 32 + lane] = make_float4(0.f, 0.f, 0.f, 0.f);
        }

        #pragma unroll
        for (int s = 0; s < 2; s++) {   // geometry, lane = edge
            const int o = obase + s;
            const int eid = o * KNN + lane;
            const int nbr = nidx[eid];
            const float dist = ndist[eid];
            const float sc = scale_compat[eid];
            float tt = 1.f - dist * dist;
            float win = fminf(fmaxf(tt * tt * tt, 0.f), 1.f);
            const float imp = sc * win;

            const float pix = inp_points[nbr * 3 + 0];
            const float piy = inp_points[nbr * 3 + 1];
            const float piz = inp_points[nbr * 3 + 2];
            const float inv = __fdividef(2.f, out_extents[o]);
            const float rx = (pix - out_points[o * 3 + 0]) * inv;
            const float ry = (piy - out_points[o * 3 + 1]) * inv;
            const float rz = (piz - out_points[o * 3 + 2]) * inv;

            const float r = sqrtf(rx * rx + ry * ry + rz * rz);
            const float linf = fmaxf(fabsf(rx), fmaxf(fabsf(ry), fabsf(rz)));
            const float sf = __fdividef(r, fmaxf(linf, 1e-12f));
            float tx = fminf(fmaxf((rx * sf * 0.5f + 0.5f) * 3.f, 0.f), 3.f);
            float ty = fminf(fmaxf((ry * sf * 0.5f + 0.5f) * 3.f, 0.f), 3.f);
            float tz = fminf(fmaxf((rz * sf * 0.5f + 0.5f) * 3.f, 0.f), 3.f);
            float t0x = fminf(floorf(tx), 2.f);
            float t0y = fminf(floorf(ty), 2.f);
            float t0z = fminf(floorf(tz), 2.f);
            int ix = (int)t0x, iy = (int)t0y, iz = (int)t0z;

            S->meta4[wid][s][lane] = make_float4(tx - t0x, ty - t0y, tz - t0z, imp);
            S->packs[wid][s][lane] = nbr | (ix << 20) | (iy << 22) | (iz << 24);

            float dsum = imp;
            #pragma unroll
            for (int off = 16; off; off >>= 1)
                dsum += __shfl_xor_sync(0xffffffffu, dsum, off);
            if (lane == 0) g_den[o] = dsum;
        }
        __syncwarp();

        {   // scatter: half-warp h -> slot h, bank (2c+h)%32 conflict-free
            const int h = lane >> 4, c = lane & 15;
            float* Bw = S->B[wid];
            const float4* m4 = S->meta4[wid][h];
            const int* pk = S->packs[wid][h];
            #pragma unroll 4
            for (int e = 0; e < KNN; e++) {
                const float4 m = m4[e];
                const int p = pk[e];
                const int nb = p & 0xFFFFF;
                const int ix = (p >> 20) & 3, iy = (p >> 22) & 3, iz = (p >> 24) & 3;
                const float fe = __ldg(&feats[nb * CIN + c]) * m.w;
                const float ax1 = fe * m.x, ax0 = fe - ax1;
                const float v01 = ax0 * m.y, v00 = ax0 - v01;
                const float v11 = ax1 * m.y, v10 = ax1 - v11;
                const float wz1 = m.z, wz0 = 1.f - m.z;
                float* Bp = Bw + ((ix * 16 + iy * 4 + iz) * 32 + c * 2 + h);
                Bp[0]   += v00 * wz0;  Bp[32]  += v00 * wz1;
                Bp[128] += v01 * wz0;  Bp[160] += v01 * wz1;
                Bp[512] += v10 * wz0;  Bp[544] += v10 * wz1;
                Bp[640] += v11 * wz0;  Bp[672] += v11 * wz1;
            }
        }
        __syncwarp();

        {   // writeout: row-major fp16, coalesced
            __half2* d0 = reinterpret_cast<__half2*>(g_B16 + (size_t)obase * KC);
            __half2* d1 = reinterpret_cast<__half2*>(g_B16 + (size_t)(obase + 1) * KC);
            const float4* Bq = reinterpret_cast<const float4*>(S->B[wid]);
            #pragma unroll 4
            for (int kt = 0; kt < 16; kt++) {
                float4 v = Bq[kt * 32 + lane];  // (kc,h0)(kc,h1)(kc+1,h0)(kc+1,h1)
                d0[kt * 32 + lane] = __floats2half2_rn(v.x, v.z);
                d1[kt * 32 + lane] = __floats2half2_rn(v.y, v.w);
            }
        }
        __syncwarp();
    }
}

// ================= K2: mma.sync fp16 GEMM + epilogue =================
#define K2_W_BYTES (2 * COUT * WSTRIDE * 2)   // 132096
#define K2_A_STAGE (MTILE * 144)              // 36864 (row stride 144B, padded)
#define K2_SMEM (K2_W_BYTES + 2 * K2_A_STAGE) // 205824

__device__ __forceinline__ void ldsm_x4(uint32_t* a, uint32_t addr) {
    asm volatile("ldmatrix.sync.aligned.m8n8.x4.shared.b16 {%0,%1,%2,%3}, [%4];"
                 : "=r"(a[0]), "=r"(a[1]), "=r"(a[2]), "=r"(a[3]) : "r"(addr));
}
__device__ __forceinline__ void mma16816(float* d, const uint32_t* a,
                                         uint32_t b0, uint32_t b1) {
    asm volatile("mma.sync.aligned.m16n8k16.row.col.f32.f16.f16.f32 "
                 "{%0,%1,%2,%3}, {%4,%5,%6,%7}, {%8,%9}, {%0,%1,%2,%3};"
                 : "+f"(d[0]), "+f"(d[1]), "+f"(d[2]), "+f"(d[3])
                 : "r"(a[0]), "r"(a[1]), "r"(a[2]), "r"(a[3]), "r"(b0), "r"(b1));
}
__device__ __forceinline__ void cp16(uint32_t dst, const void* src) {
    asm volatile("cp.async.ca.shared.global [%0], [%1], 16;"
                 :: "r"(dst), "l"(src) : "memory");
}

__global__ __launch_bounds__(256, 1)
void k2_gemm(float* __restrict__ out, const float* __restrict__ bias)
{
    extern __shared__ unsigned char raw2[];
    __half* sW = reinterpret_cast<__half*>(raw2);           // [2][32][1032]
    const uint32_t sA = smem_u32(raw2) + K2_W_BYTES;
    const int tid = threadIdx.x, w = tid >> 5, lane = tid & 31;
    const int g = lane >> 2, t = lane & 3;
    const int tile = blockIdx.x;
    const size_t abase = (size_t)tile * MTILE * KC;         // halfs

    // load W planes (L2-hot, 132 KB)
    {
        const int4* s0 = reinterpret_cast<const int4*>(g_WTh);
        const int4* s1 = reinterpret_cast<const int4*>(g_WTl);
        int4* d0 = reinterpret_cast<int4*>(sW);
        int4* d1 = reinterpret_cast<int4*>(sW + COUT * WSTRIDE);
        for (int i = tid; i < COUT * WSTRIDE / 8; i += 256) {
            d0[i] = s0[i]; d1[i] = s1[i];
        }
    }

    // issue A chunk 0 (64 halfs of K per row, 256 rows)
    #pragma unroll
    for (int q = 0; q < 8; q++) {
        int idx = tid + q * 256;               // 0..2047
        int row = idx >> 3, j = idx & 7;
        cp16(sA + row * 144 + j * 16,
             g_B16 + abase + (size_t)row * KC + j * 8);
    }
    asm volatile("cp.async.commit_group;" ::: "memory");

    float acc[2][4][4];
    #pragma unroll
    for (int mb = 0; mb < 2; mb++)
        #pragma unroll
        for (int nb = 0; nb < 4; nb++)
            #pragma unroll
            for (int i = 0; i < 4; i++) acc[mb][nb][i] = 0.f;

    const uint32_t aBase = sA + (w * 32 + (lane & 15)) * 144 + (lane >> 4) * 16;

    for (int c = 0; c < 16; c++) {
        if (c < 15) {
            #pragma unroll
            for (int q = 0; q < 8; q++) {
                int idx = tid + q * 256;
                int row = idx >> 3, j = idx & 7;
                cp16(sA + ((c + 1) & 1) * K2_A_STAGE + row * 144 + j * 16,
                     g_B16 + abase + (size_t)row * KC + (c + 1) * 64 + j * 8);
            }
            asm volatile("cp.async.commit_group;" ::: "memory");
            asm volatile("cp.async.wait_group 1;" ::: "memory");
        } else {
            asm volatile("cp.async.wait_group 0;" ::: "memory");
        }
        __syncthreads();

        const uint32_t aStage = aBase + (c & 1) * K2_A_STAGE;
        #pragma unroll
        for (int kbl = 0; kbl < 4; kbl++) {
            uint32_t a0[4], a1[4];
            ldsm_x4(a0, aStage + kbl * 32);
            ldsm_x4(a1, aStage + 16 * 144 + kbl * 32);
            const int kg = c * 64 + kbl * 16 + 2 * t;
            #pragma unroll
            for (int nb = 0; nb < 4; nb++) {
                const int n = nb * 8 + g;
                const uint32_t* wh =
                    reinterpret_cast<const uint32_t*>(sW + n * WSTRIDE + kg);
                const uint32_t* wl = reinterpret_cast<const uint32_t*>(
                    sW + COUT * WSTRIDE + n * WSTRIDE + kg);
                uint32_t wh0 = wh[0], wh1 = wh[4];   // k and k+8
                uint32_t wl0 = wl[0], wl1 = wl[4];
                mma16816(acc[0][nb], a0, wh0, wh1);
                mma16816(acc[0][nb], a0, wl0, wl1);
                mma16816(acc[1][nb], a1, wh0, wh1);
                mma16816(acc[1][nb], a1, wl0, wl1);
            }
        }
        __syncthreads();
    }

    // epilogue: normalize, bias, relu
    #pragma unroll
    for (int mb = 0; mb < 2; mb++) {
        const int row0 = tile * MTILE + w * 32 + mb * 16 + g;
        const int row1 = row0 + 8;
        float i0 = 0.f, i1 = 0.f;
        if (row0 < N_OUT_C) {
            float dn = g_den[row0];
            i0 = __fdividef(1.f, dn > 0.f ? dn : 1.f);
        }
        if (row1 < N_OUT_C) {
            float dn = g_den[row1];
            i1 = __fdividef(1.f, dn > 0.f ? dn : 1.f);
        }
        #pragma unroll
        for (int nb = 0; nb < 4; nb++) {
            const int c0 = nb * 8 + 2 * t;
            const float2 bb = *reinterpret_cast<const float2*>(bias + c0);
            if (row0 < N_OUT_C) {
                float2 v;
                v.x = fmaxf(acc[mb][nb][0] * i0 + bb.x, 0.f);
                v.y = fmaxf(acc[mb][nb][1] * i0 + bb.y, 0.f);
                *reinterpret_cast<float2*>(out + (size_t)row0 * COUT + c0) = v;
            }
            if (row1 < N_OUT_C) {
                float2 v;
                v.x = fmaxf(acc[mb][nb][2] * i1 + bb.x, 0.f);
                v.y = fmaxf(acc[mb][nb][3] * i1 + bb.y, 0.f);
                *reinterpret_cast<float2*>(out + (size_t)row1 * COUT + c0) = v;
            }
        }
    }
}

// ================= host =================
extern "C" void kernel_launch(void* const* d_in, const int* in_sizes, int n_in,
                              void* d_out, int out_size)
{
    const float* feats        = (const float*)d_in[0];
    const float* inp_points   = (const float*)d_in[1];
    const float* out_points   = (const float*)d_in[2];
    const float* out_extents  = (const float*)d_in[3];
    const float* scale_compat = (const float*)d_in[4];
    const int*   nidx         = (const int*)  d_in[5];
    const float* ndist        = (const float*)d_in[7];
    const float* kernW        = (const float*)d_in[8];
    const float* bias         = (const float*)d_in[9];
    float* out = (float*)d_out;

    cudaFuncSetAttribute(k1_scatter, cudaFuncAttributeMaxDynamicSharedMemorySize,
                         (int)sizeof(Smem1));
    cudaFuncSetAttribute(k2_gemm, cudaFuncAttributeMaxDynamicSharedMemorySize,
                         K2_SMEM);

    k0_prep<<<(KC * COUT + 255) / 256, 256>>>(kernW);
    k1_scatter<<<888, 128, sizeof(Smem1)>>>(feats, inp_points, out_points,
                                            out_extents, scale_compat, nidx, ndist);
    k2_gemm<<<NTILES, 256, K2_SMEM>>>(out, bias);
}